// round 5
// baseline (speedup 1.0000x reference)
#include <cuda_runtime.h>
#include <cuda_bf16.h>

// HierarchicalSoftmax, fused single kernel, 8-lane node groups.
//
// Inputs (metadata order):
//   d_in[0]: embeddings float32 [B, E]   (B=16384, E=128)
//   d_in[1]: word_idx   int32   [B]
//   d_in[2]: W          float32 [V-1, E] (V=131072)
//   d_in[3]: b          float32 [V-1]
// Output: float32 scalar = mean over B of sum over 17 path nodes of BCE.
//
// One warp per sample. Four 8-lane groups each handle one tree node per
// iteration; a lane owns 16 embedding floats (4 float4). 5 iterations cover
// depths 0..16 (iteration 4: only group 0 valid = root; other groups load the
// same root row -> dedupped L1 hits, result masked).

#define HS_D 17
#define TPB  256
#define WPB  8
#define MAX_BLOCKS 8192

__device__ float        g_hs_partials[MAX_BLOCKS];
__device__ unsigned int g_hs_count = 0;   // self-resetting ticket

__global__ __launch_bounds__(TPB)
void hs_fused_kernel(const float*  __restrict__ emb,
                     const int*    __restrict__ word_idx,
                     const float4* __restrict__ W4,
                     const float*  __restrict__ bias,
                     float*        __restrict__ out,
                     int B, int Vm1, float invB)
{
    const int warp = blockIdx.x * WPB + (threadIdx.x >> 5);
    const int lane = threadIdx.x & 31;
    const int g    = lane >> 3;      // node group 0..3
    const int gl   = lane & 7;       // lane within group

    float acc = 0.0f;

    if (warp < B) {
        // Lane owns embedding floats [gl*16, gl*16+16): 4 float4s, coalesced
        // (8 lanes x 64B = one 512B row per group... groups read same row).
        const float4* erow = reinterpret_cast<const float4*>(emb)
                           + (size_t)warp * 32 + gl * 4;
        const float4 e0 = erow[0];
        const float4 e1 = erow[1];
        const float4 e2 = erow[2];
        const float4 e3 = erow[3];

        // 1-based leaf heap index: ancestor at height h = (leaf1 >> h) - 1;
        // direction bit at depth d = ((leaf1 >> d) & 1) ^ 1.
        const unsigned leaf1 = (unsigned)__ldg(&word_idx[warp])
                             + (unsigned)(Vm1 + 1);

        #pragma unroll
        for (int j = 0; j < 5; ++j) {
            int idx = 4 * j + g;                   // depth slot for this group
            const bool valid = (idx < HS_D);
            if (idx > HS_D - 1) idx = HS_D - 1;    // duplicate root when invalid

            const int n = (int)((leaf1 >> (idx + 1)) - 1u);

            // 8 lanes x 4 float4 = one contiguous 512B W row per group.
            const float4* wr = W4 + (size_t)n * 32 + gl * 4;
            const float4 w0 = __ldg(wr + 0);
            const float4 w1 = __ldg(wr + 1);
            const float4 w2 = __ldg(wr + 2);
            const float4 w3 = __ldg(wr + 3);

            float p = w0.x * e0.x + w0.y * e0.y + w0.z * e0.z + w0.w * e0.w
                    + w1.x * e1.x + w1.y * e1.y + w1.z * e1.z + w1.w * e1.w
                    + w2.x * e2.x + w2.y * e2.y + w2.z * e2.z + w2.w * e2.w
                    + w3.x * e3.x + w3.y * e3.y + w3.z * e3.z + w3.w * e3.w;

            // Butterfly within the 8-lane group.
            p += __shfl_xor_sync(0xffffffffu, p, 4);
            p += __shfl_xor_sync(0xffffffffu, p, 2);
            p += __shfl_xor_sync(0xffffffffu, p, 1);

            const float s = p + __ldg(&bias[n]);
            const float t = (float)(((leaf1 >> idx) & 1u) ^ 1u);
            // fast stable BCE-with-logits
            const float bce = fmaxf(s, 0.0f) - s * t
                            + __logf(1.0f + __expf(-fabsf(s)));
            if (valid) acc += bce;
        }

        // Combine the four groups' accumulations.
        acc += __shfl_xor_sync(0xffffffffu, acc, 8);
        acc += __shfl_xor_sync(0xffffffffu, acc, 16);
    }

    // ---- block reduction + last-block grid reduction (deterministic) ----
    __shared__ float sacc[WPB];
    __shared__ bool  is_last;
    if (lane == 0) sacc[threadIdx.x >> 5] = acc;
    __syncthreads();
    if (threadIdx.x == 0) {
        float s = 0.0f;
        #pragma unroll
        for (int i = 0; i < WPB; ++i) s += sacc[i];
        g_hs_partials[blockIdx.x] = s;
        __threadfence();
        unsigned t = atomicInc(&g_hs_count, gridDim.x - 1);
        is_last = (t == gridDim.x - 1);
    }
    __syncthreads();

    if (is_last) {
        float a = 0.0f;
        for (int i = threadIdx.x; i < (int)gridDim.x; i += TPB)
            a += g_hs_partials[i];
        __shared__ float red[TPB];
        red[threadIdx.x] = a;
        __syncthreads();
        #pragma unroll
        for (int ofs = TPB / 2; ofs > 0; ofs >>= 1) {
            if (threadIdx.x < ofs) red[threadIdx.x] += red[threadIdx.x + ofs];
            __syncthreads();
        }
        if (threadIdx.x == 0) out[0] = red[0] * invB;
    }
}

extern "C" void kernel_launch(void* const* d_in, const int* in_sizes, int n_in,
                              void* d_out, int out_size)
{
    const float*  emb      = (const float*) d_in[0];
    const int*    word_idx = (const int*)   d_in[1];
    const float4* W4       = (const float4*)d_in[2];
    const float*  bias     = (const float*) d_in[3];
    float* out = (float*)d_out;

    const int B   = in_sizes[1];   // 16384
    const int Vm1 = in_sizes[3];   // V-1 = 131071

    int nblocks = (B + WPB - 1) / WPB;            // 2048
    if (nblocks > MAX_BLOCKS) nblocks = MAX_BLOCKS;

    hs_fused_kernel<<<nblocks, TPB>>>(emb, word_idx, W4, bias, out,
                                      B, Vm1, 1.0f / (float)B);
}

// round 6
// speedup vs baseline: 2.1087x; 2.1087x over previous
#include <cuda_runtime.h>
#include <cuda_bf16.h>

// HierarchicalSoftmax fused kernel, round 5.
// One warp per sample; two 16-lane halves each handle one tree node per
// iteration (lane owns 8 embedding floats). No per-node shuffle reduction:
// per-lane dot partials go to padded smem, then one transposed pass computes
// all 17 node scores + BCE in a single block, followed by one butterfly.
//
// Inputs (metadata order):
//   d_in[0]: embeddings float32 [B, E]   (B=16384, E=128)
//   d_in[1]: word_idx   int32   [B]
//   d_in[2]: W          float32 [V-1, E] (V=131072)
//   d_in[3]: b          float32 [V-1]
// Output: float32 scalar = mean over B of sum over 17 path nodes of BCE.

#define HS_D 17
#define TPB  256
#define WPB  8
#define MAX_BLOCKS 8192
#define PSTRIDE 20          // floats per node-slot (16 partials + 4 pad, 80B: 16B-aligned)
#define NSLOTS  18          // 9 iters x 2 halves (slot 17 is a discarded duplicate)

__device__ float        g_hs_partials[MAX_BLOCKS];
__device__ unsigned int g_hs_count = 0;   // self-resetting ticket

__device__ __forceinline__ unsigned long long ffma2(unsigned long long a,
                                                    unsigned long long b,
                                                    unsigned long long c)
{
    unsigned long long d;
    asm("fma.rn.f32x2 %0, %1, %2, %3;" : "=l"(d) : "l"(a), "l"(b), "l"(c));
    return d;
}

__global__ __launch_bounds__(TPB)
void hs_fused_kernel(const float*  __restrict__ emb,
                     const int*    __restrict__ word_idx,
                     const float4* __restrict__ W4,
                     const float*  __restrict__ bias,
                     float*        __restrict__ out,
                     int B, int Vm1, float invB)
{
    const int warp  = blockIdx.x * WPB + (threadIdx.x >> 5);
    const int wslot = threadIdx.x >> 5;
    const int lane  = threadIdx.x & 31;
    const int half  = lane >> 4;      // which node of the pair this lane serves
    const int hl    = lane & 15;      // lane within the 16-lane half

    __shared__ __align__(16) float spart[WPB][NSLOTS * PSTRIDE];

    float warp_sum = 0.0f;

    if (warp < B) {
        // Lane owns embedding floats [hl*8, hl*8+8) as 4 packed f32x2 pairs.
        const ulonglong2* erow = reinterpret_cast<const ulonglong2*>(emb)
                               + (size_t)warp * 16 + hl * 2;
        const ulonglong2 eA = erow[0];   // floats 0..3 of this lane's slice
        const ulonglong2 eB = erow[1];   // floats 4..7

        // 1-based leaf heap index: ancestor at height h = (leaf1 >> h) - 1;
        // direction bit at depth d = ((leaf1 >> d) & 1) ^ 1.
        const unsigned leaf1 = (unsigned)__ldg(&word_idx[warp])
                             + (unsigned)(Vm1 + 1);

        // ---- main loop: pure load -> FFMA2 -> STS (no shuffles, no BCE) ----
        #pragma unroll
        for (int j = 0; j < 9; ++j) {
            const int slot = 2 * j + half;          // 0..17
            const int idx  = (slot < HS_D) ? slot : (HS_D - 1); // dup root when invalid
            const int n    = (int)((leaf1 >> (idx + 1)) - 1u);

            // 16 lanes x 32B = one contiguous 512B W row per half-warp.
            const ulonglong2* wr = reinterpret_cast<const ulonglong2*>(W4)
                                 + (size_t)n * 16 + hl * 2;
            const ulonglong2 wA = wr[0];
            const ulonglong2 wB = wr[1];

            // Two independent packed FMA chains, then horizontal add.
            unsigned long long p0 = ffma2(wA.x, eA.x, 0ull);
            unsigned long long p1 = ffma2(wA.y, eA.y, 0ull);
            p0 = ffma2(wB.x, eB.x, p0);
            p1 = ffma2(wB.y, eB.y, p1);

            float p0l, p0h, p1l, p1h;
            asm("mov.b64 {%0,%1}, %2;" : "=f"(p0l), "=f"(p0h) : "l"(p0));
            asm("mov.b64 {%0,%1}, %2;" : "=f"(p1l), "=f"(p1h) : "l"(p1));
            spart[wslot][slot * PSTRIDE + hl] = (p0l + p0h) + (p1l + p1h);
        }
        __syncwarp();

        // ---- transposed epilogue: lane d reduces node d's 16 partials ----
        const int d = (lane < HS_D) ? lane : (HS_D - 1);   // clamped (broadcast read)
        const float4* pv = reinterpret_cast<const float4*>(
                               &spart[wslot][d * PSTRIDE]);
        const float4 a0 = pv[0];
        const float4 a1 = pv[1];
        const float4 a2 = pv[2];
        const float4 a3 = pv[3];
        const float dot = ((a0.x + a0.y) + (a0.z + a0.w))
                        + ((a1.x + a1.y) + (a1.z + a1.w))
                        + ((a2.x + a2.y) + (a2.z + a2.w))
                        + ((a3.x + a3.y) + (a3.z + a3.w));

        const int   n = (int)((leaf1 >> (d + 1)) - 1u);
        const float s = dot + __ldg(&bias[n]);
        const float t = (float)(((leaf1 >> d) & 1u) ^ 1u);
        float bce = fmaxf(s, 0.0f) - s * t + __logf(1.0f + __expf(-fabsf(s)));
        if (lane >= HS_D) bce = 0.0f;

        // One butterfly for the whole sample.
        bce += __shfl_xor_sync(0xffffffffu, bce, 16);
        bce += __shfl_xor_sync(0xffffffffu, bce, 8);
        bce += __shfl_xor_sync(0xffffffffu, bce, 4);
        bce += __shfl_xor_sync(0xffffffffu, bce, 2);
        bce += __shfl_xor_sync(0xffffffffu, bce, 1);
        warp_sum = bce;
    }

    // ---- block reduction + last-block grid reduction (deterministic) ----
    __shared__ float sacc[WPB];
    __shared__ bool  is_last;
    if (lane == 0) sacc[wslot] = warp_sum;
    __syncthreads();
    if (threadIdx.x == 0) {
        float ssum = 0.0f;
        #pragma unroll
        for (int i = 0; i < WPB; ++i) ssum += sacc[i];
        g_hs_partials[blockIdx.x] = ssum;
        __threadfence();
        unsigned tk = atomicInc(&g_hs_count, gridDim.x - 1);
        is_last = (tk == gridDim.x - 1);
    }
    __syncthreads();

    if (is_last) {
        float a = 0.0f;
        for (int i = threadIdx.x; i < (int)gridDim.x; i += TPB)
            a += g_hs_partials[i];
        __shared__ float red[TPB];
        red[threadIdx.x] = a;
        __syncthreads();
        #pragma unroll
        for (int ofs = TPB / 2; ofs > 0; ofs >>= 1) {
            if (threadIdx.x < ofs) red[threadIdx.x] += red[threadIdx.x + ofs];
            __syncthreads();
        }
        if (threadIdx.x == 0) out[0] = red[0] * invB;
    }
}

extern "C" void kernel_launch(void* const* d_in, const int* in_sizes, int n_in,
                              void* d_out, int out_size)
{
    const float*  emb      = (const float*) d_in[0];
    const int*    word_idx = (const int*)   d_in[1];
    const float4* W4       = (const float4*)d_in[2];
    const float*  bias     = (const float*) d_in[3];
    float* out = (float*)d_out;

    const int B   = in_sizes[1];   // 16384
    const int Vm1 = in_sizes[3];   // V-1 = 131071

    int nblocks = (B + WPB - 1) / WPB;            // 2048
    if (nblocks > MAX_BLOCKS) nblocks = MAX_BLOCKS;

    hs_fused_kernel<<<nblocks, TPB>>>(emb, word_idx, W4, bias, out,
                                      B, Vm1, 1.0f / (float)B);
}

// round 7
// speedup vs baseline: 2.2944x; 1.0880x over previous
#include <cuda_runtime.h>
#include <cuda_bf16.h>

// HierarchicalSoftmax fused kernel, round 6.
// One warp per sample; two 16-lane halves each handle one tree node per slot
// (lane owns 8 embedding floats). All 18 W-row loads are front-batched into
// registers (MLP=18) before any compute. Per-lane dot partials go to padded
// smem; a transposed pass computes all 17 node scores + BCE at once, then one
// butterfly + deterministic grid reduction.
//
// Inputs (metadata order):
//   d_in[0]: embeddings float32 [B, E]   (B=16384, E=128)
//   d_in[1]: word_idx   int32   [B]
//   d_in[2]: W          float32 [V-1, E] (V=131072)
//   d_in[3]: b          float32 [V-1]
// Output: float32 scalar = mean over B of sum over 17 path nodes of BCE.

#define HS_D 17
#define TPB  256
#define WPB  8
#define MAX_BLOCKS 8192
#define NSLOT 9             // slots per half; 9*2 = 18 >= 17 nodes (1 dup)
#define PSTRIDE 20          // floats per node-slot (16 partials + 4 pad; 80B, 16B-aligned)
#define ROW_U2 32           // 128 floats per row = 32 ulonglong2 (16B each)

__device__ float        g_hs_partials[MAX_BLOCKS];
__device__ unsigned int g_hs_count = 0;   // self-resetting ticket

__device__ __forceinline__ unsigned long long ffma2(unsigned long long a,
                                                    unsigned long long b,
                                                    unsigned long long c)
{
    unsigned long long d;
    asm("fma.rn.f32x2 %0, %1, %2, %3;" : "=l"(d) : "l"(a), "l"(b), "l"(c));
    return d;
}

__global__ __launch_bounds__(TPB)
void hs_fused_kernel(const float*  __restrict__ emb,
                     const int*    __restrict__ word_idx,
                     const float4* __restrict__ W4,
                     const float*  __restrict__ bias,
                     float*        __restrict__ out,
                     int B, int Vm1, float invB)
{
    const int warp  = blockIdx.x * WPB + (threadIdx.x >> 5);
    const int wslot = threadIdx.x >> 5;
    const int lane  = threadIdx.x & 31;
    const int half  = lane >> 4;      // which node of the slot-pair this lane serves
    const int hl    = lane & 15;      // lane within the 16-lane half

    __shared__ __align__(16) float spart[WPB][2 * NSLOT * PSTRIDE];

    float warp_sum = 0.0f;

    if (warp < B) {
        const ulonglong2* __restrict__ W2 =
            reinterpret_cast<const ulonglong2*>(W4);

        // Lane owns embedding floats [hl*8, hl*8+8) as 2 x 16B (4 f32x2 pairs).
        // Row = 32 ulonglong2 (512B).  <-- stride fixed vs round 5.
        const ulonglong2* erow = reinterpret_cast<const ulonglong2*>(emb)
                               + (size_t)warp * ROW_U2 + hl * 2;
        const ulonglong2 eA = erow[0];
        const ulonglong2 eB = erow[1];

        // 1-based leaf heap index: W-node at depth d = (leaf1 >> (d+1)) - 1;
        // direction bit at depth d = ((leaf1 >> d) & 1) ^ 1.
        const unsigned leaf1 = (unsigned)__ldg(&word_idx[warp])
                             + (unsigned)(Vm1 + 1);

        // ---- pass 1: issue ALL W loads back-to-back (MLP = 18) ----
        ulonglong2 wA[NSLOT], wB[NSLOT];
        #pragma unroll
        for (int j = 0; j < NSLOT; ++j) {
            const int slot = 2 * j + half;                    // 0..17
            const int idx  = (slot < HS_D) ? slot : (HS_D - 1); // dup root on 17
            const int n    = (int)((leaf1 >> (idx + 1)) - 1u);
            const ulonglong2* wr = W2 + (size_t)n * ROW_U2 + hl * 2;
            wA[j] = __ldg(wr);
            wB[j] = __ldg(wr + 1);
        }

        // ---- pass 2: packed FMA + STS (no shuffles, no BCE here) ----
        #pragma unroll
        for (int j = 0; j < NSLOT; ++j) {
            const int slot = 2 * j + half;
            unsigned long long p0 = ffma2(wA[j].x, eA.x, 0ull);
            unsigned long long p1 = ffma2(wA[j].y, eA.y, 0ull);
            p0 = ffma2(wB[j].x, eB.x, p0);
            p1 = ffma2(wB[j].y, eB.y, p1);

            float p0l, p0h, p1l, p1h;
            asm("mov.b64 {%0,%1}, %2;" : "=f"(p0l), "=f"(p0h) : "l"(p0));
            asm("mov.b64 {%0,%1}, %2;" : "=f"(p1l), "=f"(p1h) : "l"(p1));
            spart[wslot][slot * PSTRIDE + hl] = (p0l + p0h) + (p1l + p1h);
        }
        __syncwarp();

        // ---- transposed epilogue: lane d reduces node d's 16 partials ----
        const int d = (lane < HS_D) ? lane : (HS_D - 1);   // clamped duplicate
        const float4* pv = reinterpret_cast<const float4*>(
                               &spart[wslot][d * PSTRIDE]);
        const float4 a0 = pv[0];
        const float4 a1 = pv[1];
        const float4 a2 = pv[2];
        const float4 a3 = pv[3];
        const float dot = ((a0.x + a0.y) + (a0.z + a0.w))
                        + ((a1.x + a1.y) + (a1.z + a1.w))
                        + ((a2.x + a2.y) + (a2.z + a2.w))
                        + ((a3.x + a3.y) + (a3.z + a3.w));

        const int   n = (int)((leaf1 >> (d + 1)) - 1u);
        const float s = dot + __ldg(&bias[n]);
        const float t = (float)(((leaf1 >> d) & 1u) ^ 1u);
        float bce = fmaxf(s, 0.0f) - s * t + __logf(1.0f + __expf(-fabsf(s)));
        if (lane >= HS_D) bce = 0.0f;

        // One butterfly for the whole sample.
        bce += __shfl_xor_sync(0xffffffffu, bce, 16);
        bce += __shfl_xor_sync(0xffffffffu, bce, 8);
        bce += __shfl_xor_sync(0xffffffffu, bce, 4);
        bce += __shfl_xor_sync(0xffffffffu, bce, 2);
        bce += __shfl_xor_sync(0xffffffffu, bce, 1);
        warp_sum = bce;
    }

    // ---- block reduction + last-block grid reduction (deterministic) ----
    __shared__ float sacc[WPB];
    __shared__ bool  is_last;
    if (lane == 0) sacc[wslot] = warp_sum;
    __syncthreads();
    if (threadIdx.x == 0) {
        float ssum = 0.0f;
        #pragma unroll
        for (int i = 0; i < WPB; ++i) ssum += sacc[i];
        g_hs_partials[blockIdx.x] = ssum;
        __threadfence();
        unsigned tk = atomicInc(&g_hs_count, gridDim.x - 1);
        is_last = (tk == gridDim.x - 1);
    }
    __syncthreads();

    if (is_last) {
        float a = 0.0f;
        for (int i = threadIdx.x; i < (int)gridDim.x; i += TPB)
            a += g_hs_partials[i];
        __shared__ float red[TPB];
        red[threadIdx.x] = a;
        __syncthreads();
        #pragma unroll
        for (int ofs = TPB / 2; ofs > 0; ofs >>= 1) {
            if (threadIdx.x < ofs) red[threadIdx.x] += red[threadIdx.x + ofs];
            __syncthreads();
        }
        if (threadIdx.x == 0) out[0] = red[0] * invB;
    }
}

extern "C" void kernel_launch(void* const* d_in, const int* in_sizes, int n_in,
                              void* d_out, int out_size)
{
    const float*  emb      = (const float*) d_in[0];
    const int*    word_idx = (const int*)   d_in[1];
    const float4* W4       = (const float4*)d_in[2];
    const float*  bias     = (const float*) d_in[3];
    float* out = (float*)d_out;

    const int B   = in_sizes[1];   // 16384
    const int Vm1 = in_sizes[3];   // V-1 = 131071

    int nblocks = (B + WPB - 1) / WPB;            // 2048
    if (nblocks > MAX_BLOCKS) nblocks = MAX_BLOCKS;

    hs_fused_kernel<<<nblocks, TPB>>>(emb, word_idx, W4, bias, out,
                                      B, Vm1, 1.0f / (float)B);
}